// round 11
// baseline (speedup 1.0000x reference)
#include <cuda_runtime.h>
#include <cuda_bf16.h>

#define BATCH 65536
#define EMBED 128
#define HIST 5
#define NEG 2

// 16-lane reduction: offsets 8/4/2/1 never cross the 16-lane half-warp boundary,
// so both halves reduce independently with full-width shfl.
__device__ __forceinline__ float sum16(float v) {
    #pragma unroll
    for (int o = 8; o; o >>= 1) v += __shfl_xor_sync(0xFFFFFFFFu, v, o);
    return v;
}

__device__ __forceinline__ float sq4(float4 a, float4 b) {
    float dx = a.x - b.x, dy = a.y - b.y, dz = a.z - b.z, dw = a.w - b.w;
    return dx*dx + dy*dy + dz*dz + dw*dw;
}

__device__ __forceinline__ float sq8(float4 a0, float4 a1, float4 b0, float4 b1) {
    return sq4(a0, b0) + sq4(a1, b1);
}

__device__ __forceinline__ float log_sigmoid(float x) {
    // stable: min(x,0) - log1p(exp(-|x|))
    return fminf(x, 0.0f) - log1pf(__expf(-fabsf(x)));
}

__global__ __launch_bounds__(128, 5)
void htne_kernel(const int* __restrict__ xs,
                 const int* __restrict__ ys,
                 const float* __restrict__ e_times,
                 const int* __restrict__ hs,
                 const float* __restrict__ h_times,
                 const int* __restrict__ neg_node,
                 const float* __restrict__ h_times_mask,
                 const float* __restrict__ emb,
                 const float* __restrict__ delta_tab,
                 float* __restrict__ out)
{
    const int warp = (blockIdx.x * blockDim.x + threadIdx.x) >> 5;
    const int sub  = (threadIdx.x >> 4) & 1;   // which 16-lane group
    const int sl   = threadIdx.x & 15;         // sub-lane 0..15
    const int b    = warp * 2 + sub;           // batch element of this half-warp
    if (b >= BATCH) return;

    // ---- index + scalar loads (uniform per half-warp) ----
    const int xi = __ldg(xs + b);
    const int yi = __ldg(ys + b);
    int hi[HIST];
    #pragma unroll
    for (int j = 0; j < HIST; j++) hi[j] = __ldg(hs + b * HIST + j);
    int ni[NEG];
    #pragma unroll
    for (int k = 0; k < NEG; k++) ni[k] = __ldg(neg_node + b * NEG + k);

    // ---- 9 row gathers, 2 float4 per lane (18 LDG.128 per warp, MLP=18) ----
    const float4* __restrict__ emb4 = (const float4*)emb;
    const int row4 = EMBED / 4;  // 32 float4 per row

    const float4* xp = emb4 + (size_t)xi * row4;
    float4 xe0 = __ldg(xp + sl), xe1 = __ldg(xp + sl + 16);
    const float4* yp = emb4 + (size_t)yi * row4;
    float4 ye0 = __ldg(yp + sl), ye1 = __ldg(yp + sl + 16);
    float4 he0[HIST], he1[HIST];
    #pragma unroll
    for (int j = 0; j < HIST; j++) {
        const float4* hp = emb4 + (size_t)hi[j] * row4;
        he0[j] = __ldg(hp + sl); he1[j] = __ldg(hp + sl + 16);
    }
    float4 ne0[NEG], ne1[NEG];
    #pragma unroll
    for (int k = 0; k < NEG; k++) {
        const float4* np = emb4 + (size_t)ni[k] * row4;
        ne0[k] = __ldg(np + sl); ne1[k] = __ldg(np + sl + 16);
    }

    const float et    = __ldg(e_times + b);
    const float delta = __ldg(delta_tab + xi);
    float ht[HIST], hm[HIST];
    #pragma unroll
    for (int j = 0; j < HIST; j++) {
        ht[j] = __ldg(h_times + b * HIST + j);
        hm[j] = __ldg(h_times_mask + b * HIST + j);
    }

    // ---- per-lane squared-distance partials ----
    float p_mu_p = sq8(xe0, xe1, ye0, ye1);
    float alpha_p[HIST];
    #pragma unroll
    for (int j = 0; j < HIST; j++) alpha_p[j] = sq8(xe0, xe1, he0[j], he1[j]);
    float n_mu_p[NEG];
    #pragma unroll
    for (int k = 0; k < NEG; k++) n_mu_p[k] = sq8(xe0, xe1, ne0[k], ne1[k]);
    float n_alpha_p[HIST][NEG];
    #pragma unroll
    for (int j = 0; j < HIST; j++)
        #pragma unroll
        for (int k = 0; k < NEG; k++) n_alpha_p[j][k] = sq8(he0[j], he1[j], ne0[k], ne1[k]);

    // ---- primary reductions: 5 alpha + 1 p_mu (each serves both elements) ----
    float alpha[HIST];
    #pragma unroll
    for (int j = 0; j < HIST; j++) alpha[j] = -sum16(alpha_p[j]);
    float p_mu = -sum16(p_mu_p);

    // ---- softmax weights + decay (uniform across the 16-lane group) ----
    float amax = alpha[0];
    #pragma unroll
    for (int j = 1; j < HIST; j++) amax = fmaxf(amax, alpha[j]);
    float attn[HIST], esum = 0.0f;
    #pragma unroll
    for (int j = 0; j < HIST; j++) { attn[j] = __expf(alpha[j] - amax); esum += attn[j]; }
    float inv = 1.0f / esum;

    float p_lambda = p_mu;
    float w[HIST];  // attn * decay (uniform across group)
    #pragma unroll
    for (int j = 0; j < HIST; j++) {
        float d_time = fabsf(et - ht[j]);
        float decay = __expf(delta * d_time) * hm[j];
        w[j] = attn[j] * inv * decay;
        p_lambda += w[j] * alpha[j];
    }

    // ---- fused negative-path reductions: 2 total ----
    // n_lambda[k] = n_mu[k] + sum_j w_j * n_alpha[j][k]
    //            = -sum16( n_mu_p[k] + sum_j w_j * n_alpha_p[j][k] )
    float n_lambda[NEG];
    #pragma unroll
    for (int k = 0; k < NEG; k++) {
        float t = n_mu_p[k];
        #pragma unroll
        for (int j = 0; j < HIST; j++) t += w[j] * n_alpha_p[j][k];
        n_lambda[k] = -sum16(t);
    }

    float loss = log_sigmoid(p_lambda);
    #pragma unroll
    for (int k = 0; k < NEG; k++) loss -= log_sigmoid(n_lambda[k]);

    if (sl == 0) out[b] = loss;
}

extern "C" void kernel_launch(void* const* d_in, const int* in_sizes, int n_in,
                              void* d_out, int out_size)
{
    const int*   xs        = (const int*)  d_in[0];
    const int*   ys        = (const int*)  d_in[1];
    const float* e_times   = (const float*)d_in[2];
    const int*   hs        = (const int*)  d_in[3];
    const float* h_times   = (const float*)d_in[4];
    const int*   neg_node  = (const int*)  d_in[5];
    const float* h_mask    = (const float*)d_in[6];
    const float* emb       = (const float*)d_in[7];
    const float* delta_tab = (const float*)d_in[8];
    float* out = (float*)d_out;

    const int threads = 128;                       // 4 warps/block, 8 elements/block
    const int blocks = (BATCH * 16) / threads;     // 8192
    htne_kernel<<<blocks, threads>>>(xs, ys, e_times, hs, h_times, neg_node,
                                     h_mask, emb, delta_tab, out);
}